// round 6
// baseline (speedup 1.0000x reference)
#include <cuda_runtime.h>
#include <cuda_fp16.h>
#include <cstdint>

// Problem constants
#define BB 4
#define SS 2048
#define DD 1024
#define NHH 16
#define ADIM 64
#define MTOT (BB*SS)          // 8192

// ---------------------------------------------------------------------------
// Scratch (allocation-free rule: __device__ globals) — all fp16
// ---------------------------------------------------------------------------
__device__ __align__(1024) __half g_qkv[(size_t)MTOT * 3 * DD];   // 48 MB
__device__ __align__(1024) __half g_o[(size_t)MTOT * DD];         // 16 MB
__device__ __align__(1024) __half g_a[(size_t)MTOT * DD];         // rounded iQ
__device__ __align__(1024) __half g_b[(size_t)3 * DD * DD];       // rounded w_qkv
__device__ __align__(1024) __half g_w[(size_t)DD * DD];           // rounded w_out

// ---------------------------------------------------------------------------
// helpers
// ---------------------------------------------------------------------------
__device__ __forceinline__ uint32_t smem_u32(const void* p) {
    uint32_t a;
    asm("{ .reg .u64 t; cvta.to.shared.u64 t, %1; cvt.u32.u64 %0, t; }" : "=r"(a) : "l"(p));
    return a;
}

__device__ __forceinline__ void mma_f16(float c[4], const uint32_t a[4],
                                        uint32_t b0, uint32_t b1) {
    asm volatile(
        "mma.sync.aligned.m16n8k16.row.col.f32.f16.f16.f32 "
        "{%0,%1,%2,%3}, {%4,%5,%6,%7}, {%8,%9}, {%0,%1,%2,%3};\n"
        : "+f"(c[0]), "+f"(c[1]), "+f"(c[2]), "+f"(c[3])
        : "r"(a[0]), "r"(a[1]), "r"(a[2]), "r"(a[3]), "r"(b0), "r"(b1));
}

#define LDM_X4(r0,r1,r2,r3, addr) \
    asm volatile("ldmatrix.sync.aligned.m8n8.x4.shared.b16 {%0,%1,%2,%3}, [%4];" \
        : "=r"(r0), "=r"(r1), "=r"(r2), "=r"(r3) : "r"(addr))

#define LDM_X4_T(r0,r1,r2,r3, addr) \
    asm volatile("ldmatrix.sync.aligned.m8n8.x4.trans.shared.b16 {%0,%1,%2,%3}, [%4];" \
        : "=r"(r0), "=r"(r1), "=r"(r2), "=r"(r3) : "r"(addr))

__device__ __forceinline__ void cp16(uint32_t dst, const void* src) {
    asm volatile("cp.async.cg.shared.global [%0], [%1], 16;" :: "r"(dst), "l"(src));
}
#define CP_COMMIT() asm volatile("cp.async.commit_group;" ::: "memory")

__device__ __forceinline__ uint32_t pack_h2(float lo, float hi) {
    __half2 h = __floats2half2_rn(lo, hi);
    return *(uint32_t*)&h;
}

// ---------------------------------------------------------------------------
// fp32 -> fp16 pre-round (8 elements/thread, 16B stores)
// ---------------------------------------------------------------------------
__global__ void __launch_bounds__(256) f16_round_kernel(
    const float4* __restrict__ in, uint4* __restrict__ out)
{
    int i = blockIdx.x * 256 + threadIdx.x;
    float4 a = in[2 * i], b = in[2 * i + 1];
    uint4 o;
    o.x = pack_h2(a.x, a.y);
    o.y = pack_h2(a.z, a.w);
    o.z = pack_h2(b.x, b.y);
    o.w = pack_h2(b.z, b.w);
    out[i] = o;
}

// ---------------------------------------------------------------------------
// fp16 GEMM: C[M,N] = A[M,K] * B[N,K]^T  (fp32 accum).
// CTA tile 128x128x64; 128 threads = 4 warps in 2x2 grid, warp tile 64x64.
// 3-stage cp.async pipeline, ONE __syncthreads per k-tile.
// ---------------------------------------------------------------------------
#define GST 72                                   // smem row stride in halfs
#define GROWB (GST * 2)                          // 144 bytes
#define GMAT_BYTES (128 * GROWB)                 // 18432 per matrix
#define GSTAGE_BYTES (2 * GMAT_BYTES)            // 36864
#define GSM_BYTES (3 * GSTAGE_BYTES)             // 110592

template<bool HALF_OUT>
__global__ void __launch_bounds__(128, 2) gemm_f16_kernel(
    const __half* __restrict__ A, const __half* __restrict__ Bm,
    void* __restrict__ Cv, int N, int K)
{
    extern __shared__ char smc[];
    const uint32_t sm_base = smem_u32(smc);

    const int tid  = threadIdx.x;
    const int warp = tid >> 5, lane = tid & 31;
    const int g = lane >> 2, t = lane & 3;
    const int wm = warp & 1;        // 64-row half
    const int wn = warp >> 1;       // 64-col half
    const int m0 = blockIdx.y * 128, n0 = blockIdx.x * 128;
    const int NKT = K >> 6;

    // ldmatrix lane address parts (bytes)
    const uint32_t aLane = (uint32_t)(wm * 64 + (lane & 15)) * GROWB + (lane & 16);
    const uint32_t bLane = (uint32_t)(wn * 64 + (lane & 15)) * GROWB + (lane & 16);

    float acc[4][8][4];
    #pragma unroll
    for (int i = 0; i < 4; i++)
        #pragma unroll
        for (int j = 0; j < 8; j++)
            #pragma unroll
            for (int k = 0; k < 4; k++) acc[i][j][k] = 0.f;

    auto issue = [&](int kt) {
        uint32_t sA = sm_base + (uint32_t)(kt % 3) * GSTAGE_BYTES;
        uint32_t sB = sA + GMAT_BYTES;
        #pragma unroll
        for (int i = 0; i < 8; i++) {
            int idx = tid + i * 128;          // 0..1023
            int row = idx >> 3, ch = idx & 7; // 8 x 16B per 64-half row
            uint32_t so = (uint32_t)row * GROWB + ch * 16;
            cp16(sA + so, &A[(size_t)(m0 + row) * K + kt * 64 + ch * 8]);
            cp16(sB + so, &Bm[(size_t)(n0 + row) * K + kt * 64 + ch * 8]);
        }
    };

    issue(0); CP_COMMIT();
    issue(1); CP_COMMIT();

    for (int kt = 0; kt < NKT; kt++) {
        if (kt + 1 < NKT) {
            asm volatile("cp.async.wait_group 1;" ::: "memory");
        } else {
            asm volatile("cp.async.wait_group 0;" ::: "memory");
        }
        __syncthreads();                     // arrivals visible + prev stage free
        if (kt + 2 < NKT) { issue(kt + 2); CP_COMMIT(); }

        uint32_t sA = sm_base + (uint32_t)(kt % 3) * GSTAGE_BYTES;
        uint32_t sB = sA + GMAT_BYTES;

        #pragma unroll
        for (int ks = 0; ks < 4; ks++) {
            uint32_t a[4][4];
            #pragma unroll
            for (int mt = 0; mt < 4; mt++)
                LDM_X4(a[mt][0], a[mt][1], a[mt][2], a[mt][3],
                       sA + aLane + (uint32_t)(mt * 16) * GROWB + ks * 32);
            #pragma unroll
            for (int p = 0; p < 4; p++) {
                uint32_t b0, b1, b2, b3;
                LDM_X4(b0, b1, b2, b3,
                       sB + bLane + (uint32_t)(p * 16) * GROWB + ks * 32);
                #pragma unroll
                for (int mt = 0; mt < 4; mt++) {
                    mma_f16(acc[mt][2 * p],     a[mt], b0, b2);
                    mma_f16(acc[mt][2 * p + 1], a[mt], b1, b3);
                }
            }
        }
    }

    #pragma unroll
    for (int mt = 0; mt < 4; mt++) {
        int r0 = m0 + wm * 64 + mt * 16 + g;
        #pragma unroll
        for (int nt = 0; nt < 8; nt++) {
            int c0 = n0 + wn * 64 + nt * 8 + 2 * t;
            if (HALF_OUT) {
                __half* Ch = (__half*)Cv;
                *(uint32_t*)&Ch[(size_t)r0 * N + c0]       = pack_h2(acc[mt][nt][0], acc[mt][nt][1]);
                *(uint32_t*)&Ch[(size_t)(r0 + 8) * N + c0] = pack_h2(acc[mt][nt][2], acc[mt][nt][3]);
            } else {
                float* Cf = (float*)Cv;
                *(float2*)&Cf[(size_t)r0 * N + c0]       = make_float2(acc[mt][nt][0], acc[mt][nt][1]);
                *(float2*)&Cf[(size_t)(r0 + 8) * N + c0] = make_float2(acc[mt][nt][2], acc[mt][nt][3]);
            }
        }
    }
}

// ---------------------------------------------------------------------------
// Fused squared-ReLU attention, fp16 mma, double-buffered K/V,
// ONE __syncthreads per key-tile.
// Grid: (S/128, NH, B). Block 256 (8 warps x 16 q-rows).
// ---------------------------------------------------------------------------
#define AST 72
#define AROWB (AST * 2)                          // 144 bytes
#define ATILE_B (128 * AROWB)                    // 18432 per tile
// layout: Q | K0 | K1 | V0 | V1
#define AQ_OFF   0
#define AK_OFF   ATILE_B
#define AV_OFF   (3 * ATILE_B)
#define ATTN_SMEM_BYTES (5 * ATILE_B)            // 92160

__global__ void __launch_bounds__(256, 2) attn_kernel(
    const __half* __restrict__ qkv, const float* __restrict__ sn_bias,
    __half* __restrict__ o_out)
{
    extern __shared__ char smc[];
    const uint32_t base = smem_u32(smc);

    const int tid  = threadIdx.x;
    const int warp = tid >> 5, lane = tid & 31;
    const int g = lane >> 2, t = lane & 3;
    const int qt = blockIdx.x, h = blockIdx.y, b = blockIdx.z;
    const float bias = sn_bias[0];

    // ldmatrix lane address parts (bytes)
    const uint32_t qLane = (uint32_t)(warp * 16 + (lane & 15)) * AROWB + (lane & 16);
    const uint32_t kLane = (uint32_t)(lane & 15) * AROWB + (lane & 16);

    auto issueKV = [&](int kt) {
        int buf = kt & 1;
        #pragma unroll
        for (int i = 0; i < 4; i++) {
            int idx = tid + i * 256;
            int row = idx >> 3, ch = idx & 7;
            size_t gp = ((size_t)(b * SS + kt * 128 + row)) * (3 * DD) + h * ADIM + ch * 8;
            uint32_t so = (uint32_t)row * AROWB + ch * 16;
            cp16(base + AK_OFF + buf * ATILE_B + so, &qkv[gp + DD]);
            cp16(base + AV_OFF + buf * ATILE_B + so, &qkv[gp + 2 * DD]);
        }
    };

    // prologue: Q + first K/V tile
    {
        #pragma unroll
        for (int i = 0; i < 4; i++) {
            int idx = tid + i * 256;
            int row = idx >> 3, ch = idx & 7;
            size_t gp = ((size_t)(b * SS + qt * 128 + row)) * (3 * DD) + h * ADIM + ch * 8;
            cp16(base + AQ_OFF + (uint32_t)row * AROWB + ch * 16, &qkv[gp]);
        }
        issueKV(0);
        CP_COMMIT();
    }

    float Oacc[8][4];
    #pragma unroll
    for (int i = 0; i < 8; i++)
        #pragma unroll
        for (int j = 0; j < 4; j++) Oacc[i][j] = 0.f;
    float rsum0 = 0.f, rsum1 = 0.f;

    for (int kt = 0; kt < 16; kt++) {
        const int buf = kt & 1;
        asm volatile("cp.async.wait_group 0;" ::: "memory");   // tile kt arrived
        __syncthreads();                   // publish arrivals + prev buf free
        if (kt + 1 < 16) { issueKV(kt + 1); CP_COMMIT(); }

        const uint32_t sK = base + AK_OFF + buf * ATILE_B;
        const uint32_t sV = base + AV_OFF + buf * ATILE_B;

        // ---- S = Q K^T  (warp: 16 q-rows x 128 keys), fp32 accum
        float Sacc[16][4];
        #pragma unroll
        for (int i = 0; i < 16; i++)
            #pragma unroll
            for (int j = 0; j < 4; j++) Sacc[i][j] = 0.f;

        #pragma unroll
        for (int ks = 0; ks < 4; ks++) {
            uint32_t a[4];
            LDM_X4(a[0], a[1], a[2], a[3], base + AQ_OFF + qLane + ks * 32);
            #pragma unroll
            for (int p = 0; p < 8; p++) {
                uint32_t b0, b1, b2, b3;
                LDM_X4(b0, b1, b2, b3, sK + kLane + (uint32_t)(p * 16) * AROWB + ks * 32);
                mma_f16(Sacc[2 * p],     a, b0, b2);
                mma_f16(Sacc[2 * p + 1], a, b1, b3);
            }
        }

        // ---- t = relu(S/8 + bias)^2 in place, rowsum in fp32
        #pragma unroll
        for (int nt = 0; nt < 16; nt++) {
            float v0 = fmaxf(Sacc[nt][0] * 0.125f + bias, 0.f); v0 *= v0;
            float v1 = fmaxf(Sacc[nt][1] * 0.125f + bias, 0.f); v1 *= v1;
            float v2 = fmaxf(Sacc[nt][2] * 0.125f + bias, 0.f); v2 *= v2;
            float v3 = fmaxf(Sacc[nt][3] * 0.125f + bias, 0.f); v3 *= v3;
            rsum0 += v0 + v1;
            rsum1 += v2 + v3;
            Sacc[nt][0] = v0; Sacc[nt][1] = v1; Sacc[nt][2] = v2; Sacc[nt][3] = v3;
        }

        // ---- O += t * V : A-frag is a straight f32->f16x2 pack of Sacc
        #pragma unroll
        for (int kk = 0; kk < 8; kk++) {
            uint32_t aF[4];
            aF[0] = pack_h2(Sacc[2 * kk][0],     Sacc[2 * kk][1]);
            aF[1] = pack_h2(Sacc[2 * kk][2],     Sacc[2 * kk][3]);
            aF[2] = pack_h2(Sacc[2 * kk + 1][0], Sacc[2 * kk + 1][1]);
            aF[3] = pack_h2(Sacc[2 * kk + 1][2], Sacc[2 * kk + 1][3]);
            #pragma unroll
            for (int p = 0; p < 4; p++) {
                uint32_t b0, b1, b2, b3;
                LDM_X4_T(b0, b1, b2, b3,
                         sV + (uint32_t)(kk * 16 + (lane & 15)) * AROWB + p * 32 + (lane & 16));
                mma_f16(Oacc[2 * p],     aF, b0, b1);
                mma_f16(Oacc[2 * p + 1], aF, b2, b3);
            }
        }
    }

    // ---- normalize and write O as fp16 (feeds out-proj GEMM)
    rsum0 += __shfl_xor_sync(0xffffffffu, rsum0, 1);
    rsum0 += __shfl_xor_sync(0xffffffffu, rsum0, 2);
    rsum1 += __shfl_xor_sync(0xffffffffu, rsum1, 1);
    rsum1 += __shfl_xor_sync(0xffffffffu, rsum1, 2);
    float inv0 = 1.f / (rsum0 + 1e-32f);
    float inv1 = 1.f / (rsum1 + 1e-32f);

    const int row0 = warp * 16 + g;
    size_t ob0 = ((size_t)(b * SS + qt * 128 + row0)) * DD + h * ADIM;
    size_t ob1 = ob0 + 8 * DD;
    #pragma unroll
    for (int dt = 0; dt < 8; dt++) {
        int c = dt * 8 + 2 * t;
        *(uint32_t*)&o_out[ob0 + c] = pack_h2(Oacc[dt][0] * inv0, Oacc[dt][1] * inv0);
        *(uint32_t*)&o_out[ob1 + c] = pack_h2(Oacc[dt][2] * inv1, Oacc[dt][3] * inv1);
    }
}

// ---------------------------------------------------------------------------
// Launch
// ---------------------------------------------------------------------------
extern "C" void kernel_launch(void* const* d_in, const int* in_sizes, int n_in,
                              void* d_out, int out_size)
{
    const float* iQ      = (const float*)d_in[0];
    const float* w_qkv   = (const float*)d_in[1];
    const float* w_out   = (const float*)d_in[2];
    const float* sn_bias = (const float*)d_in[3];
    float* out = (float*)d_out;
    (void)in_sizes; (void)n_in; (void)out_size;

    cudaFuncSetAttribute(attn_kernel,
                         cudaFuncAttributeMaxDynamicSharedMemorySize, ATTN_SMEM_BYTES);
    cudaFuncSetAttribute(gemm_f16_kernel<true>,
                         cudaFuncAttributeMaxDynamicSharedMemorySize, GSM_BYTES);
    cudaFuncSetAttribute(gemm_f16_kernel<false>,
                         cudaFuncAttributeMaxDynamicSharedMemorySize, GSM_BYTES);

    __half *qkvp = nullptr, *op = nullptr, *ap = nullptr, *bp = nullptr, *wp = nullptr;
    cudaGetSymbolAddress((void**)&qkvp, g_qkv);
    cudaGetSymbolAddress((void**)&op, g_o);
    cudaGetSymbolAddress((void**)&ap, g_a);
    cudaGetSymbolAddress((void**)&bp, g_b);
    cudaGetSymbolAddress((void**)&wp, g_w);

    // 0) pre-round inputs to fp16
    f16_round_kernel<<<(MTOT * DD) / 2048, 256>>>((const float4*)iQ, (uint4*)ap);
    f16_round_kernel<<<(3 * DD * DD) / 2048, 256>>>((const float4*)w_qkv, (uint4*)bp);
    f16_round_kernel<<<(DD * DD) / 2048, 256>>>((const float4*)w_out, (uint4*)wp);

    // 1) qkv = iQ @ w_qkv^T  -> half [8192, 3072]
    gemm_f16_kernel<true><<<dim3(3 * DD / 128, MTOT / 128), 128, GSM_BYTES>>>(
        ap, bp, qkvp, 3 * DD, DD);

    // 2) fused squared-ReLU attention -> half g_o [8192, 1024]
    attn_kernel<<<dim3(SS / 128, NHH, BB), 256, ATTN_SMEM_BYTES>>>(
        qkvp, sn_bias, op);

    // 3) out = o @ w_out^T  -> float d_out
    gemm_f16_kernel<false><<<dim3(DD / 128, MTOT / 128), 128, GSM_BYTES>>>(
        op, wp, out, DD, DD);
}